// round 6
// baseline (speedup 1.0000x reference)
#include <cuda_runtime.h>
#include <cstdint>

// ---------------------------------------------------------------------------
// Problem constants
// ---------------------------------------------------------------------------
#define TT   2048      // B*S total rows
#define DIM  7168
#define NH   64        // heads
#define HD   128       // head dim
#define RD   64        // rope dims
#define QL   1536
#define HHD  8192      // NH*HD
#define SQ   1024      // sequence (per batch)
#define EPSV 1e-6f
#define SCALEV 0.08838834764831845f   // 128^-0.5
#define KSPL 16        // split-K factor for the kw GEMM

// ---------------------------------------------------------------------------
// Scratch (device globals: allocation-free, graph-capture safe)
// ---------------------------------------------------------------------------
__device__ float    g_q[TT * HHD];          // 64 MB : q (tf32 bits after fused rope)
__device__ unsigned g_qrt[TT * QL];         // 12.6MB: qr tf32 bits
__device__ unsigned g_wqt[HHD * QL];        // 50 MB : Wq^T tf32 bits [N][K]
__device__ unsigned g_bkw[256 * DIM];       // 7.3MB : (Wk || Wproj || 0)^T tf32 bits
__device__ float    g_kwp[KSPL * TT * 256]; // 33 MB : split-K partials
__device__ float    g_kw[TT * 256];         // kp (cols 0-127) | w (cols 128-191)
__device__ unsigned g_ktf[TT * HD];         // final k, tf32 bits

// ---------------------------------------------------------------------------
// helpers
// ---------------------------------------------------------------------------
__device__ __forceinline__ unsigned f2tf(float f) {
    unsigned u;
    asm("cvt.rna.tf32.f32 %0, %1;" : "=r"(u) : "f"(f));
    return u;
}

__device__ __forceinline__ uint32_t smem_u32(const void* p) {
    uint32_t a;
    asm("{ .reg .u64 t; cvta.to.shared.u64 t, %1; cvt.u32.u64 %0, t; }"
        : "=r"(a) : "l"(p));
    return a;
}

#define CP_ASYNC16(dst, src) \
    asm volatile("cp.async.cg.shared.global [%0], [%1], 16;" \
                 :: "r"(dst), "l"(src) : "memory")
#define CP_COMMIT() asm volatile("cp.async.commit_group;" ::: "memory")
#define CP_WAIT(n)  asm volatile("cp.async.wait_group %0;" :: "n"(n) : "memory")

__device__ __forceinline__ void mma_tf32(float c[4], const unsigned a[4],
                                         const unsigned b[2]) {
    asm volatile(
        "mma.sync.aligned.m16n8k8.row.col.f32.tf32.tf32.f32 "
        "{%0,%1,%2,%3}, {%4,%5,%6,%7}, {%8,%9}, {%0,%1,%2,%3};"
        : "+f"(c[0]), "+f"(c[1]), "+f"(c[2]), "+f"(c[3])
        : "r"(a[0]), "r"(a[1]), "r"(a[2]), "r"(a[3]), "r"(b[0]), "r"(b[1]));
}

// smem row stride: 32 k + 4 pad u32 = 144 B
#define RST 36
// 512-thread GEMM: A tile 256x32 (36864 B) then B tile 128x32 (18432 B)
#define GQ_B_OFF 36864
#define GQ_STAGE 55296
#define GQ_SMEM  (2 * GQ_STAGE)    // 110592
// scores: Q tile 128x32 (18432 B) then K tile 256x32 (36864 B)
#define SC_K_OFF 18432
#define SC_STAGE 55296
#define SC_SMEM  (2 * SC_STAGE)

// ---------------------------------------------------------------------------
// Elementwise fp32 -> tf32 bits (float4 granularity)
// ---------------------------------------------------------------------------
__global__ __launch_bounds__(256) void cvt_tf(const float* __restrict__ in,
                                              unsigned* __restrict__ outb) {
    const size_t i4 = (size_t)blockIdx.x * 256 + threadIdx.x;
    float4 v = *(const float4*)(in + i4 * 4);
    uint4 t;
    t.x = f2tf(v.x); t.y = f2tf(v.y); t.z = f2tf(v.z); t.w = f2tf(v.w);
    *(uint4*)(outb + i4 * 4) = t;
}

// ---------------------------------------------------------------------------
// Transpose + tf32-convert:  Wqt[n][k] = tf32(Wq[k][n])
// ---------------------------------------------------------------------------
__global__ __launch_bounds__(256) void transpose_tf(const float* __restrict__ W,
                                                    unsigned* __restrict__ Wt) {
    __shared__ float tile[32][33];
    const int tx = threadIdx.x, ty = threadIdx.y;
    const int n0 = blockIdx.x * 32, k0 = blockIdx.y * 32;
#pragma unroll
    for (int j = 0; j < 32; j += 8)
        tile[ty + j][tx] = W[(size_t)(k0 + ty + j) * HHD + n0 + tx];
    __syncthreads();
#pragma unroll
    for (int j = 0; j < 32; j += 8)
        Wt[(size_t)(n0 + ty + j) * QL + k0 + tx] = f2tf(tile[tx][ty + j]);
}

// ---------------------------------------------------------------------------
// Pack (Wk || Wproj || 0) transposed -> g_bkw[n][k], tf32 bits.  n in [0,256)
// ---------------------------------------------------------------------------
__global__ __launch_bounds__(256) void pack_kw(const float* __restrict__ wk,
                                               const float* __restrict__ wpr,
                                               unsigned* __restrict__ Bkw) {
    __shared__ float tile[32][33];
    const int tx = threadIdx.x, ty = threadIdx.y;
    const int n0 = blockIdx.x * 32, k0 = blockIdx.y * 32;
#pragma unroll
    for (int j = 0; j < 32; j += 8) {
        int k = k0 + ty + j, n = n0 + tx;
        float v = (n < HD) ? wk[(size_t)k * HD + n]
                           : ((n < HD + NH) ? wpr[(size_t)k * NH + (n - HD)] : 0.f);
        tile[ty + j][tx] = v;
    }
    __syncthreads();
#pragma unroll
    for (int j = 0; j < 32; j += 8)
        Bkw[(size_t)(n0 + ty + j) * DIM + k0 + tx] = f2tf(tile[tx][ty + j]);
}

// ---------------------------------------------------------------------------
// 512-thread double-buffered mma.sync tf32 GEMM.
// C = A[M,Ktot] @ B[N,Ktot]^T, block tile 256x128, warp tile 64x32 (4x4 warps).
// CVTA:  A is fp32, convert in-register after LDS (for x).
// ROPE:  fused interleaved RoPE over first RD cols of each head + tf32 output.
// Split-K along gridDim.z writes partials at C + z*gridDim.y*256*N.
// ---------------------------------------------------------------------------
template <bool CVTA, bool ROPE>
__global__ __launch_bounds__(512, 1) void tc_gemm512(const unsigned* __restrict__ A,
                                                     const unsigned* __restrict__ B,
                                                     float* __restrict__ C,
                                                     const float* __restrict__ cosv,
                                                     const float* __restrict__ sinv,
                                                     int Ktot, int N, int nchunks) {
    extern __shared__ char smem[];
    const uint32_t sb = smem_u32(smem);
    const int tid = threadIdx.x;
    const int lane = tid & 31, wid = tid >> 5;
    const int warp_m = wid >> 2, warp_n = wid & 3;   // 4 x 4
    const int g = lane >> 2, qd = lane & 3;
    const int m0 = blockIdx.y * 256;
    const int n0 = blockIdx.x * 128;
    const int c0 = blockIdx.z * nchunks;
    C += (size_t)blockIdx.z * gridDim.y * 256 * N;

    auto load_stage = [&](int c, int s) {
        const int kt = c * 32;
        const uint32_t base = sb + s * GQ_STAGE;
#pragma unroll
        for (int r = 0; r < 4; r++) {                 // A: 256 rows
            int lin = r * 512 + tid;
            int row = lin >> 3, c4 = lin & 7;
            CP_ASYNC16(base + row * 144 + c4 * 16,
                       A + (size_t)(m0 + row) * Ktot + kt + c4 * 4);
        }
#pragma unroll
        for (int r = 0; r < 2; r++) {                 // B: 128 rows
            int lin = r * 512 + tid;
            int row = lin >> 3, c4 = lin & 7;
            CP_ASYNC16(base + GQ_B_OFF + row * 144 + c4 * 16,
                       B + (size_t)(n0 + row) * Ktot + kt + c4 * 4);
        }
        CP_COMMIT();
    };

    float acc[4][4][4];
#pragma unroll
    for (int i = 0; i < 4; i++)
#pragma unroll
        for (int j = 0; j < 4; j++)
#pragma unroll
            for (int r = 0; r < 4; r++) acc[i][j][r] = 0.f;

    load_stage(c0, 0);

    for (int i = 0; i < nchunks; i++) {
        const int s = i & 1;
        if (i + 1 < nchunks) { load_stage(c0 + i + 1, s ^ 1); CP_WAIT(1); }
        else                 { CP_WAIT(0); }
        __syncthreads();

        const unsigned* As = (const unsigned*)(smem + s * GQ_STAGE);
        const unsigned* Bs = (const unsigned*)(smem + s * GQ_STAGE + GQ_B_OFF);
#pragma unroll
        for (int k8 = 0; k8 < 4; k8++) {
            unsigned a[4][4], b[4][2];
#pragma unroll
            for (int mt = 0; mt < 4; mt++) {
                int mrow = warp_m * 64 + mt * 16 + g;
                a[mt][0] = As[mrow * RST + k8 * 8 + qd];
                a[mt][1] = As[(mrow + 8) * RST + k8 * 8 + qd];
                a[mt][2] = As[mrow * RST + k8 * 8 + qd + 4];
                a[mt][3] = As[(mrow + 8) * RST + k8 * 8 + qd + 4];
                if (CVTA) {
#pragma unroll
                    for (int u = 0; u < 4; u++) a[mt][u] = f2tf(__uint_as_float(a[mt][u]));
                }
            }
#pragma unroll
            for (int nt = 0; nt < 4; nt++) {
                int ncol = warp_n * 32 + nt * 8 + g;
                b[nt][0] = Bs[ncol * RST + k8 * 8 + qd];
                b[nt][1] = Bs[ncol * RST + k8 * 8 + qd + 4];
            }
#pragma unroll
            for (int mt = 0; mt < 4; mt++)
#pragma unroll
                for (int nt = 0; nt < 4; nt++) mma_tf32(acc[mt][nt], a[mt], b[nt]);
        }
        __syncthreads();
    }

#pragma unroll
    for (int mt = 0; mt < 4; mt++) {
        int r0 = m0 + warp_m * 64 + mt * 16 + g;     // token rows r0, r0+8
#pragma unroll
        for (int nt = 0; nt < 4; nt++) {
            int d = warp_n * 32 + nt * 8 + qd * 2;   // col within head (BN==HD)
            float v00 = acc[mt][nt][0], v01 = acc[mt][nt][1];
            float v10 = acc[mt][nt][2], v11 = acc[mt][nt][3];
            if (ROPE) {
                if (d < RD) {
                    float c0r = cosv[(size_t)r0 * RD + d];
                    float s0r = sinv[(size_t)r0 * RD + d];
                    float c1r = cosv[(size_t)(r0 + 8) * RD + d];
                    float s1r = sinv[(size_t)(r0 + 8) * RD + d];
                    float o00 = v00 * c0r - v01 * s0r;
                    float o01 = v01 * c0r + v00 * s0r;
                    float o10 = v10 * c1r - v11 * s1r;
                    float o11 = v11 * c1r + v10 * s1r;
                    v00 = o00; v01 = o01; v10 = o10; v11 = o11;
                }
                v00 = __uint_as_float(f2tf(v00));
                v01 = __uint_as_float(f2tf(v01));
                v10 = __uint_as_float(f2tf(v10));
                v11 = __uint_as_float(f2tf(v11));
            }
            int cc = n0 + warp_n * 32 + nt * 8 + qd * 2;
            *(float2*)(C + (size_t)r0 * N + cc)       = make_float2(v00, v01);
            *(float2*)(C + (size_t)(r0 + 8) * N + cc) = make_float2(v10, v11);
        }
    }
}

// ---------------------------------------------------------------------------
// Reduce split-K partials: g_kw = sum_z g_kwp[z]
// ---------------------------------------------------------------------------
__global__ __launch_bounds__(256) void reduce_kw(const float* __restrict__ part,
                                                 float* __restrict__ outb) {
    const int i4 = blockIdx.x * 256 + threadIdx.x;
    const size_t SZ = (size_t)TT * 256;
    float4 s = *(const float4*)(part + (size_t)i4 * 4);
#pragma unroll
    for (int z = 1; z < KSPL; z++) {
        float4 v = *(const float4*)(part + z * SZ + (size_t)i4 * 4);
        s.x += v.x; s.y += v.y; s.z += v.z; s.w += v.w;
    }
    *(float4*)(outb + (size_t)i4 * 4) = s;
}

// ---------------------------------------------------------------------------
// LayerNorm(kp)*gamma+beta, RoPE on first RD dims, output tf32 bits -> g_ktf
// ---------------------------------------------------------------------------
__global__ __launch_bounds__(128) void ln_rope_k(const float* __restrict__ kw,
                                                 const float* __restrict__ cosv,
                                                 const float* __restrict__ sinv,
                                                 const float* __restrict__ gamma,
                                                 const float* __restrict__ beta,
                                                 unsigned* __restrict__ kout) {
    const int t = blockIdx.x;
    const int d = threadIdx.x;
    float v = kw[(size_t)t * 256 + d];
    float s1 = v, s2 = v * v;
#pragma unroll
    for (int off = 16; off; off >>= 1) {
        s1 += __shfl_xor_sync(0xffffffffu, s1, off);
        s2 += __shfl_xor_sync(0xffffffffu, s2, off);
    }
    __shared__ float r1[4], r2[4];
    if ((d & 31) == 0) { r1[d >> 5] = s1; r2[d >> 5] = s2; }
    __syncthreads();
    float sum = r1[0] + r1[1] + r1[2] + r1[3];
    float sq  = r2[0] + r2[1] + r2[2] + r2[3];
    float mu  = sum * (1.f / HD);
    float var = sq * (1.f / HD) - mu * mu;
    float kn  = (v - mu) * rsqrtf(var + EPSV) * gamma[d] + beta[d];

    __shared__ float ks[HD];
    ks[d] = kn;
    __syncthreads();
    float out = kn;
    if (d < RD) {
        float c = cosv[t * RD + (d & ~1)];
        float s = sinv[t * RD + (d & ~1)];
        float partner = ks[d ^ 1];
        out = ((d & 1) == 0) ? (kn * c - partner * s)
                             : (kn * c + partner * s);
    }
    kout[t * HD + d] = f2tf(out);
}

// ---------------------------------------------------------------------------
// scores[b,i,k] = scale * sum_h w[b,i,h] * relu( q[b,i,h,:] . k[b,k,:] )
// 512 threads. Block = 2 queries (128 rows) x 256 keys. Warp tile 64x32.
// warp_m = wid>>3 (query), warp_n = wid&7 (32-key strip).
// ---------------------------------------------------------------------------
__global__ __launch_bounds__(512, 1) void scores_tc(const unsigned* __restrict__ q,
                                                    const unsigned* __restrict__ ktf,
                                                    const float* __restrict__ kw,
                                                    float* __restrict__ out) {
    extern __shared__ char smem[];
    const uint32_t sb = smem_u32(smem);
    const int tid = threadIdx.x;
    const int lane = tid & 31, wid = tid >> 5;
    const int warp_m = wid >> 3, warp_n = wid & 7;   // 2 x 8
    const int g = lane >> 2, qd = lane & 3;

    const int t0 = blockIdx.y * 2;
    const int b  = t0 >> 10;
    const int k0 = blockIdx.x * 256;

    const float* wrow = kw + (size_t)(t0 + warp_m) * 256 + 128;
    float w0[4], w1[4];
#pragma unroll
    for (int mt = 0; mt < 4; mt++) {
        w0[mt] = wrow[mt * 16 + g] * SCALEV;
        w1[mt] = wrow[mt * 16 + g + 8] * SCALEV;
    }

    const unsigned* qbase = q + (size_t)t0 * HHD;
    const unsigned* kbase = ktf + (size_t)(b * SQ + k0) * HD;

    auto load_stage = [&](int c, int s) {
        const int d0 = c * 32;
        const uint32_t base = sb + s * SC_STAGE;
#pragma unroll
        for (int r = 0; r < 2; r++) {                 // Q: 128 rows
            int lin = r * 512 + tid;
            int row = lin >> 3, c4 = lin & 7;
            CP_ASYNC16(base + row * 144 + c4 * 16,
                       qbase + (size_t)(row >> 6) * HHD + (row & 63) * HD + d0 + c4 * 4);
        }
#pragma unroll
        for (int r = 0; r < 4; r++) {                 // K: 256 rows
            int lin = r * 512 + tid;
            int row = lin >> 3, c4 = lin & 7;
            CP_ASYNC16(base + SC_K_OFF + row * 144 + c4 * 16,
                       kbase + (size_t)row * HD + d0 + c4 * 4);
        }
        CP_COMMIT();
    };

    float acc[4][4][4];
#pragma unroll
    for (int i = 0; i < 4; i++)
#pragma unroll
        for (int j = 0; j < 4; j++)
#pragma unroll
            for (int r = 0; r < 4; r++) acc[i][j][r] = 0.f;

    load_stage(0, 0);

#pragma unroll
    for (int i = 0; i < 4; i++) {
        const int s = i & 1;
        if (i + 1 < 4) { load_stage(i + 1, s ^ 1); CP_WAIT(1); }
        else           { CP_WAIT(0); }
        __syncthreads();

        const unsigned* Qs = (const unsigned*)(smem + s * SC_STAGE);
        const unsigned* Ks = (const unsigned*)(smem + s * SC_STAGE + SC_K_OFF);
#pragma unroll
        for (int k8 = 0; k8 < 4; k8++) {
            unsigned a[4][4], bfr[4][2];
#pragma unroll
            for (int mt = 0; mt < 4; mt++) {
                int mrow = warp_m * 64 + mt * 16 + g;
                a[mt][0] = Qs[mrow * RST + k8 * 8 + qd];
                a[mt][1] = Qs[(mrow + 8) * RST + k8 * 8 + qd];
                a[mt][2] = Qs[mrow * RST + k8 * 8 + qd + 4];
                a[mt][3] = Qs[(mrow + 8) * RST + k8 * 8 + qd + 4];
            }
#pragma unroll
            for (int nt = 0; nt < 4; nt++) {
                int ncol = warp_n * 32 + nt * 8 + g;
                bfr[nt][0] = Ks[ncol * RST + k8 * 8 + qd];
                bfr[nt][1] = Ks[ncol * RST + k8 * 8 + qd + 4];
            }
#pragma unroll
            for (int mt = 0; mt < 4; mt++)
#pragma unroll
                for (int nt = 0; nt < 4; nt++) mma_tf32(acc[mt][nt], a[mt], bfr[nt]);
        }
        __syncthreads();
    }

    // weighted relu + head reduction (intra-warp shfl)
    float p[4][2];
#pragma unroll
    for (int nt = 0; nt < 4; nt++) { p[nt][0] = 0.f; p[nt][1] = 0.f; }
#pragma unroll
    for (int mt = 0; mt < 4; mt++) {
#pragma unroll
        for (int nt = 0; nt < 4; nt++) {
            p[nt][0] += w0[mt] * fmaxf(acc[mt][nt][0], 0.f)
                      + w1[mt] * fmaxf(acc[mt][nt][2], 0.f);
            p[nt][1] += w0[mt] * fmaxf(acc[mt][nt][1], 0.f)
                      + w1[mt] * fmaxf(acc[mt][nt][3], 0.f);
        }
    }
#pragma unroll
    for (int nt = 0; nt < 4; nt++) {
#pragma unroll
        for (int off = 4; off <= 16; off <<= 1) {
            p[nt][0] += __shfl_xor_sync(0xffffffffu, p[nt][0], off);
            p[nt][1] += __shfl_xor_sync(0xffffffffu, p[nt][1], off);
        }
    }

    if (lane < 4) {
        float* o = out + (size_t)(t0 + warp_m) * SQ + k0 + warp_n * 32;
#pragma unroll
        for (int nt = 0; nt < 4; nt++)
            *(float2*)(o + nt * 8 + lane * 2) = make_float2(p[nt][0], p[nt][1]);
    }
}

// ---------------------------------------------------------------------------
// launch
// ---------------------------------------------------------------------------
extern "C" void kernel_launch(void* const* d_in, const int* in_sizes, int n_in,
                              void* d_out, int out_size) {
    const float* x    = (const float*)d_in[0];   // [2048, 7168]
    const float* qr   = (const float*)d_in[1];   // [2048, 1536]
    const float* cosv = (const float*)d_in[2];   // [2048, 64]
    const float* sinv = (const float*)d_in[3];   // [2048, 64]
    const float* wqb  = (const float*)d_in[4];   // [1536, 8192]
    const float* wk   = (const float*)d_in[5];   // [7168, 128]
    const float* wpr  = (const float*)d_in[6];   // [7168, 64]
    const float* gam  = (const float*)d_in[7];   // [128]
    const float* bet  = (const float*)d_in[8];   // [128]
    float* out = (float*)d_out;

    float *q, *kwp, *kwb;
    unsigned *qrt, *wqt, *bkw, *ktf;
    cudaGetSymbolAddress((void**)&q,   g_q);
    cudaGetSymbolAddress((void**)&qrt, g_qrt);
    cudaGetSymbolAddress((void**)&wqt, g_wqt);
    cudaGetSymbolAddress((void**)&bkw, g_bkw);
    cudaGetSymbolAddress((void**)&kwp, g_kwp);
    cudaGetSymbolAddress((void**)&kwb, g_kw);
    cudaGetSymbolAddress((void**)&ktf, g_ktf);

    static bool attr_set = false;
    if (!attr_set) {
        cudaFuncSetAttribute(tc_gemm512<false, true>,
                             cudaFuncAttributeMaxDynamicSharedMemorySize, GQ_SMEM);
        cudaFuncSetAttribute(tc_gemm512<true, false>,
                             cudaFuncAttributeMaxDynamicSharedMemorySize, GQ_SMEM);
        cudaFuncSetAttribute(scores_tc,
                             cudaFuncAttributeMaxDynamicSharedMemorySize, SC_SMEM);
        attr_set = true;
    }

    // operand prep
    cvt_tf<<<(TT * QL / 4) / 256, 256>>>(qr, qrt);
    transpose_tf<<<dim3(HHD / 32, QL / 32), dim3(32, 8)>>>(wqb, wqt);
    pack_kw<<<dim3(8, DIM / 32), dim3(32, 8)>>>(wk, wpr, bkw);

    // q = rope(qr @ Wq) -> tf32 bits   [2048 x 8192 x 1536], fused epilogue
    tc_gemm512<false, true><<<dim3(HHD / 128, TT / 256, 1), 512, GQ_SMEM>>>(
        qrt, wqt, q, cosv, sinv, QL, HHD, QL / 32);
    // kp|w = x @ (Wk||Wproj)  split-K=16 partials (x converted in-register)
    tc_gemm512<true, false><<<dim3(2, TT / 256, KSPL), 512, GQ_SMEM>>>(
        (const unsigned*)x, bkw, kwp, cosv, sinv, DIM, 256, DIM / 32 / KSPL);
    reduce_kw<<<(TT * 256 / 4) / 256, 256>>>(kwp, kwb);

    // layernorm + rope k -> tf32 bits
    ln_rope_k<<<TT, 128>>>(kwb, cosv, sinv, gam, bet, ktf);
    // scores
    scores_tc<<<dim3(SQ / 256, TT / 2), 512, SC_SMEM>>>((const unsigned*)q, ktf, kwb, out);
}

// round 7
// speedup vs baseline: 1.1767x; 1.1767x over previous
#include <cuda_runtime.h>
#include <cstdint>

// ---------------------------------------------------------------------------
// Problem constants
// ---------------------------------------------------------------------------
#define TT   2048      // B*S total rows
#define DIM  7168
#define NH   64        // heads
#define HD   128       // head dim
#define RD   64        // rope dims
#define QL   1536
#define HHD  8192      // NH*HD
#define SQ   1024      // sequence (per batch)
#define EPSV 1e-6f
#define SCALEV 0.08838834764831845f   // 128^-0.5
#define KSPL 8         // split-K factor for the kw GEMM

// pair permutation within 8-element k-groups: fragments (qd, qd+4) -> adjacent
#define KPERM(k) (((k) & ~7) | (((k) & 3) << 1) | (((k) >> 2) & 1))

// ---------------------------------------------------------------------------
// Scratch (device globals: allocation-free, graph-capture safe)
// ---------------------------------------------------------------------------
__device__ unsigned g_q[TT * HHD];          // 64 MB : q tf32 bits, k-permuted
__device__ unsigned g_qrt[TT * QL];         // 12.6MB: qr tf32 bits, k-permuted
__device__ unsigned g_xt[TT * DIM];         // 58 MB : x  tf32 bits, k-permuted
__device__ unsigned g_wqt[HHD * QL];        // 50 MB : Wq^T tf32 bits, k-permuted
__device__ unsigned g_bkw[256 * DIM];       // 7.3MB : (Wk||Wproj||0)^T tf32, k-permuted
__device__ float    g_kwp[KSPL * TT * 256]; // 16 MB : split-K partials
__device__ float    g_kw[TT * 256];         // kp (cols 0-127) | w (cols 128-191)
__device__ unsigned g_ktf[TT * HD];         // final k, tf32 bits, k-permuted

// ---------------------------------------------------------------------------
// helpers
// ---------------------------------------------------------------------------
__device__ __forceinline__ unsigned f2tf(float f) {
    unsigned u;
    asm("cvt.rna.tf32.f32 %0, %1;" : "=r"(u) : "f"(f));
    return u;
}

__device__ __forceinline__ uint32_t smem_u32(const void* p) {
    uint32_t a;
    asm("{ .reg .u64 t; cvta.to.shared.u64 t, %1; cvt.u32.u64 %0, t; }"
        : "=r"(a) : "l"(p));
    return a;
}

#define CP_ASYNC16(dst, src) \
    asm volatile("cp.async.cg.shared.global [%0], [%1], 16;" \
                 :: "r"(dst), "l"(src) : "memory")
#define CP_COMMIT() asm volatile("cp.async.commit_group;" ::: "memory")
#define CP_WAIT(n)  asm volatile("cp.async.wait_group %0;" :: "n"(n) : "memory")

__device__ __forceinline__ void mma_tf32(float c[4], const unsigned a[4],
                                         const unsigned b[2]) {
    asm volatile(
        "mma.sync.aligned.m16n8k8.row.col.f32.tf32.tf32.f32 "
        "{%0,%1,%2,%3}, {%4,%5,%6,%7}, {%8,%9}, {%0,%1,%2,%3};"
        : "+f"(c[0]), "+f"(c[1]), "+f"(c[2]), "+f"(c[3])
        : "r"(a[0]), "r"(a[1]), "r"(a[2]), "r"(a[3]), "r"(b[0]), "r"(b[1]));
}

// smem tile row stride: 32 k + 8 pad u32 = 160 B (conflict-free LDS.64 pattern)
#define RST 40
#define TS_B_OFF 20480                     // 128 * 160
#define STAGE_BYTES 40960                  // A + B tiles per stage
#define SMEM_PIPE (2 * STAGE_BYTES)        // 81920

// ---------------------------------------------------------------------------
// Elementwise fp32 -> tf32 bits, k-permuted within 8-groups
// ---------------------------------------------------------------------------
__global__ __launch_bounds__(256) void cvt_tf_perm(const float* __restrict__ in,
                                                   unsigned* __restrict__ outb) {
    const size_t i0 = ((size_t)blockIdx.x * 256 + threadIdx.x) * 4;
    float4 v = *(const float4*)(in + i0);
    outb[KPERM(i0 + 0)] = f2tf(v.x);
    outb[KPERM(i0 + 1)] = f2tf(v.y);
    outb[KPERM(i0 + 2)] = f2tf(v.z);
    outb[KPERM(i0 + 3)] = f2tf(v.w);
}

// ---------------------------------------------------------------------------
// Transpose + tf32-convert + k-permute:  Wqt[n][perm(k)] = tf32(Wq[k][n])
// ---------------------------------------------------------------------------
__global__ __launch_bounds__(256) void transpose_tf(const float* __restrict__ W,
                                                    unsigned* __restrict__ Wt) {
    __shared__ float tile[32][33];
    const int tx = threadIdx.x, ty = threadIdx.y;
    const int n0 = blockIdx.x * 32, k0 = blockIdx.y * 32;
#pragma unroll
    for (int j = 0; j < 32; j += 8)
        tile[ty + j][tx] = W[(size_t)(k0 + ty + j) * HHD + n0 + tx];
    __syncthreads();
#pragma unroll
    for (int j = 0; j < 32; j += 8)
        Wt[(size_t)(n0 + ty + j) * QL + KPERM(k0 + tx)] = f2tf(tile[tx][ty + j]);
}

// ---------------------------------------------------------------------------
// Pack (Wk || Wproj || 0) transposed, tf32, k-permuted -> g_bkw[n][perm(k)]
// ---------------------------------------------------------------------------
__global__ __launch_bounds__(256) void pack_kw(const float* __restrict__ wk,
                                               const float* __restrict__ wpr,
                                               unsigned* __restrict__ Bkw) {
    __shared__ float tile[32][33];
    const int tx = threadIdx.x, ty = threadIdx.y;
    const int n0 = blockIdx.x * 32, k0 = blockIdx.y * 32;
#pragma unroll
    for (int j = 0; j < 32; j += 8) {
        int k = k0 + ty + j, n = n0 + tx;
        float v = (n < HD) ? wk[(size_t)k * HD + n]
                           : ((n < HD + NH) ? wpr[(size_t)k * NH + (n - HD)] : 0.f);
        tile[ty + j][tx] = v;
    }
    __syncthreads();
#pragma unroll
    for (int j = 0; j < 32; j += 8)
        Bkw[(size_t)(n0 + ty + j) * DIM + KPERM(k0 + tx)] = f2tf(tile[tx][ty + j]);
}

// ---------------------------------------------------------------------------
// Double-buffered mma.sync tf32 GEMM, all operands tf32 bits, k-permuted.
// C = A[M,Ktot] @ B[N,Ktot]^T, block 128x128, 8 warps (2x4), warp 64x32.
// ROPE: fused interleaved RoPE + tf32-convert + k-permuted store (q path);
//       else plain fp32 float2 store (kw partials path).
// 2 CTAs/SM.
// ---------------------------------------------------------------------------
template <bool ROPE>
__global__ __launch_bounds__(256, 2) void tc_gemm(const unsigned* __restrict__ A,
                                                  const unsigned* __restrict__ B,
                                                  void* __restrict__ Cv,
                                                  const float* __restrict__ cosv,
                                                  const float* __restrict__ sinv,
                                                  int Ktot, int N, int nchunks) {
    extern __shared__ char smem[];
    const uint32_t sb = smem_u32(smem);
    const int tid = threadIdx.x;
    const int lane = tid & 31, wid = tid >> 5;
    const int warp_m = wid >> 2, warp_n = wid & 3;
    const int g = lane >> 2, qd = lane & 3;
    const int m0 = blockIdx.y * 128;
    const int n0 = blockIdx.x * 128;
    const int c0 = blockIdx.z * nchunks;
    float* C = (float*)Cv + (size_t)blockIdx.z * gridDim.y * 128 * N;

    auto load_stage = [&](int c, int s) {
        const int kt = c * 32;
        const uint32_t base = sb + s * STAGE_BYTES;
#pragma unroll
        for (int r = 0; r < 4; r++) {
            int lin = r * 256 + tid;
            int row = lin >> 3, c4 = lin & 7;
            CP_ASYNC16(base + row * 160 + c4 * 16,
                       A + (size_t)(m0 + row) * Ktot + kt + c4 * 4);
        }
#pragma unroll
        for (int r = 0; r < 4; r++) {
            int lin = r * 256 + tid;
            int row = lin >> 3, c4 = lin & 7;
            CP_ASYNC16(base + TS_B_OFF + row * 160 + c4 * 16,
                       B + (size_t)(n0 + row) * Ktot + kt + c4 * 4);
        }
        CP_COMMIT();
    };

    float acc[4][4][4];
#pragma unroll
    for (int i = 0; i < 4; i++)
#pragma unroll
        for (int j = 0; j < 4; j++)
#pragma unroll
            for (int r = 0; r < 4; r++) acc[i][j][r] = 0.f;

    load_stage(c0, 0);

    for (int i = 0; i < nchunks; i++) {
        const int s = i & 1;
        if (i + 1 < nchunks) { load_stage(c0 + i + 1, s ^ 1); CP_WAIT(1); }
        else                 { CP_WAIT(0); }
        __syncthreads();

        const unsigned* As = (const unsigned*)(smem + s * STAGE_BYTES);
        const unsigned* Bs = (const unsigned*)(smem + s * STAGE_BYTES + TS_B_OFF);
#pragma unroll
        for (int k8 = 0; k8 < 4; k8++) {
            const int ko = k8 * 8 + qd * 2;
            unsigned a[4][4], b[4][2];
#pragma unroll
            for (int mt = 0; mt < 4; mt++) {
                int mrow = warp_m * 64 + mt * 16 + g;
                uint2 lo = *(const uint2*)&As[mrow * RST + ko];
                uint2 hi = *(const uint2*)&As[(mrow + 8) * RST + ko];
                a[mt][0] = lo.x; a[mt][1] = hi.x; a[mt][2] = lo.y; a[mt][3] = hi.y;
            }
#pragma unroll
            for (int nt = 0; nt < 4; nt++) {
                int ncol = warp_n * 32 + nt * 8 + g;
                uint2 bv = *(const uint2*)&Bs[ncol * RST + ko];
                b[nt][0] = bv.x; b[nt][1] = bv.y;
            }
#pragma unroll
            for (int mt = 0; mt < 4; mt++)
#pragma unroll
                for (int nt = 0; nt < 4; nt++) mma_tf32(acc[mt][nt], a[mt], b[nt]);
        }
        __syncthreads();
    }

#pragma unroll
    for (int mt = 0; mt < 4; mt++) {
        int r0 = m0 + warp_m * 64 + mt * 16 + g;   // token rows r0, r0+8
#pragma unroll
        for (int nt = 0; nt < 4; nt++) {
            int cc = n0 + warp_n * 32 + nt * 8 + qd * 2;   // even global col
            float v00 = acc[mt][nt][0], v01 = acc[mt][nt][1];
            float v10 = acc[mt][nt][2], v11 = acc[mt][nt][3];
            if (ROPE) {
                int d = cc & (HD - 1);              // col within head (BN==HD)
                if (d < RD) {
                    float c0r = cosv[(size_t)r0 * RD + d];
                    float s0r = sinv[(size_t)r0 * RD + d];
                    float c1r = cosv[(size_t)(r0 + 8) * RD + d];
                    float s1r = sinv[(size_t)(r0 + 8) * RD + d];
                    float o00 = v00 * c0r - v01 * s0r;
                    float o01 = v01 * c0r + v00 * s0r;
                    float o10 = v10 * c1r - v11 * s1r;
                    float o11 = v11 * c1r + v10 * s1r;
                    v00 = o00; v01 = o01; v10 = o10; v11 = o11;
                }
                unsigned* Cq = (unsigned*)Cv;
                int p0 = KPERM(cc), p1 = KPERM(cc + 1);
                Cq[(size_t)r0 * N + p0]       = f2tf(v00);
                Cq[(size_t)r0 * N + p1]       = f2tf(v01);
                Cq[(size_t)(r0 + 8) * N + p0] = f2tf(v10);
                Cq[(size_t)(r0 + 8) * N + p1] = f2tf(v11);
            } else {
                *(float2*)(C + (size_t)r0 * N + cc)       = make_float2(v00, v01);
                *(float2*)(C + (size_t)(r0 + 8) * N + cc) = make_float2(v10, v11);
            }
        }
    }
}

// ---------------------------------------------------------------------------
// Reduce split-K partials: g_kw = sum_z g_kwp[z]
// ---------------------------------------------------------------------------
__global__ __launch_bounds__(256) void reduce_kw(const float* __restrict__ part,
                                                 float* __restrict__ outb) {
    const int i4 = blockIdx.x * 256 + threadIdx.x;
    const size_t SZ = (size_t)TT * 256;
    float4 s = *(const float4*)(part + (size_t)i4 * 4);
#pragma unroll
    for (int z = 1; z < KSPL; z++) {
        float4 v = *(const float4*)(part + z * SZ + (size_t)i4 * 4);
        s.x += v.x; s.y += v.y; s.z += v.z; s.w += v.w;
    }
    *(float4*)(outb + (size_t)i4 * 4) = s;
}

// ---------------------------------------------------------------------------
// LayerNorm(kp)*gamma+beta, RoPE, output tf32 bits k-permuted -> g_ktf
// ---------------------------------------------------------------------------
__global__ __launch_bounds__(128) void ln_rope_k(const float* __restrict__ kw,
                                                 const float* __restrict__ cosv,
                                                 const float* __restrict__ sinv,
                                                 const float* __restrict__ gamma,
                                                 const float* __restrict__ beta,
                                                 unsigned* __restrict__ kout) {
    const int t = blockIdx.x;
    const int d = threadIdx.x;
    float v = kw[(size_t)t * 256 + d];
    float s1 = v, s2 = v * v;
#pragma unroll
    for (int off = 16; off; off >>= 1) {
        s1 += __shfl_xor_sync(0xffffffffu, s1, off);
        s2 += __shfl_xor_sync(0xffffffffu, s2, off);
    }
    __shared__ float r1[4], r2[4];
    if ((d & 31) == 0) { r1[d >> 5] = s1; r2[d >> 5] = s2; }
    __syncthreads();
    float sum = r1[0] + r1[1] + r1[2] + r1[3];
    float sq  = r2[0] + r2[1] + r2[2] + r2[3];
    float mu  = sum * (1.f / HD);
    float var = sq * (1.f / HD) - mu * mu;
    float kn  = (v - mu) * rsqrtf(var + EPSV) * gamma[d] + beta[d];

    __shared__ float ks[HD];
    ks[d] = kn;
    __syncthreads();
    float out = kn;
    if (d < RD) {
        float c = cosv[t * RD + (d & ~1)];
        float s = sinv[t * RD + (d & ~1)];
        float partner = ks[d ^ 1];
        out = ((d & 1) == 0) ? (kn * c - partner * s)
                             : (kn * c + partner * s);
    }
    kout[(size_t)t * HD + KPERM(d)] = f2tf(out);
}

// ---------------------------------------------------------------------------
// scores[b,i,k] = scale * sum_h w[b,i,h] * relu( q[b,i,h,:] . k[b,k,:] )
// Block = 2 queries (128 rows) x 128 keys, 256 threads, 2 CTAs/SM.
// Q/K both tf32 bits, k-permuted -> LDS.64 fragment loads.
// ---------------------------------------------------------------------------
__global__ __launch_bounds__(256, 2) void scores_tc(const unsigned* __restrict__ q,
                                                    const unsigned* __restrict__ ktf,
                                                    const float* __restrict__ kw,
                                                    float* __restrict__ out) {
    extern __shared__ char smem[];
    const uint32_t sb = smem_u32(smem);
    const int tid = threadIdx.x;
    const int lane = tid & 31, wid = tid >> 5;
    const int warp_m = wid >> 2, warp_n = wid & 3;
    const int g = lane >> 2, qd = lane & 3;

    const int t0 = blockIdx.y * 2;
    const int b  = t0 >> 10;
    const int k0 = blockIdx.x * 128;

    const float* wrow = kw + (size_t)(t0 + warp_m) * 256 + 128;
    float w0[4], w1[4];
#pragma unroll
    for (int mt = 0; mt < 4; mt++) {
        w0[mt] = wrow[mt * 16 + g] * SCALEV;
        w1[mt] = wrow[mt * 16 + g + 8] * SCALEV;
    }

    const unsigned* qbase = q + (size_t)t0 * HHD;
    const unsigned* kbase = ktf + (size_t)(b * SQ + k0) * HD;

    auto load_stage = [&](int c, int s) {
        const int d0 = c * 32;
        const uint32_t base = sb + s * STAGE_BYTES;
#pragma unroll
        for (int r = 0; r < 4; r++) {
            int lin = r * 256 + tid;
            int row = lin >> 3, c4 = lin & 7;
            CP_ASYNC16(base + row * 160 + c4 * 16,
                       qbase + (size_t)(row >> 6) * HHD + (row & 63) * HD + d0 + c4 * 4);
        }
#pragma unroll
        for (int r = 0; r < 4; r++) {
            int lin = r * 256 + tid;
            int row = lin >> 3, c4 = lin & 7;
            CP_ASYNC16(base + TS_B_OFF + row * 160 + c4 * 16,
                       kbase + (size_t)row * HD + d0 + c4 * 4);
        }
        CP_COMMIT();
    };

    float acc[4][4][4];
#pragma unroll
    for (int i = 0; i < 4; i++)
#pragma unroll
        for (int j = 0; j < 4; j++)
#pragma unroll
            for (int r = 0; r < 4; r++) acc[i][j][r] = 0.f;

    load_stage(0, 0);

#pragma unroll
    for (int i = 0; i < 4; i++) {
        const int s = i & 1;
        if (i + 1 < 4) { load_stage(i + 1, s ^ 1); CP_WAIT(1); }
        else           { CP_WAIT(0); }
        __syncthreads();

        const unsigned* Qs = (const unsigned*)(smem + s * STAGE_BYTES);
        const unsigned* Ks = (const unsigned*)(smem + s * STAGE_BYTES + TS_B_OFF);
#pragma unroll
        for (int k8 = 0; k8 < 4; k8++) {
            const int ko = k8 * 8 + qd * 2;
            unsigned a[4][4], bfr[4][2];
#pragma unroll
            for (int mt = 0; mt < 4; mt++) {
                int mrow = warp_m * 64 + mt * 16 + g;
                uint2 lo = *(const uint2*)&Qs[mrow * RST + ko];
                uint2 hi = *(const uint2*)&Qs[(mrow + 8) * RST + ko];
                a[mt][0] = lo.x; a[mt][1] = hi.x; a[mt][2] = lo.y; a[mt][3] = hi.y;
            }
#pragma unroll
            for (int nt = 0; nt < 4; nt++) {
                int ncol = warp_n * 32 + nt * 8 + g;
                uint2 bv = *(const uint2*)&Ks[ncol * RST + ko];
                bfr[nt][0] = bv.x; bfr[nt][1] = bv.y;
            }
#pragma unroll
            for (int mt = 0; mt < 4; mt++)
#pragma unroll
                for (int nt = 0; nt < 4; nt++) mma_tf32(acc[mt][nt], a[mt], bfr[nt]);
        }
        __syncthreads();
    }

    // weighted relu + head reduction (intra-warp shfl)
    float p[4][2];
#pragma unroll
    for (int nt = 0; nt < 4; nt++) { p[nt][0] = 0.f; p[nt][1] = 0.f; }
#pragma unroll
    for (int mt = 0; mt < 4; mt++) {
#pragma unroll
        for (int nt = 0; nt < 4; nt++) {
            p[nt][0] += w0[mt] * fmaxf(acc[mt][nt][0], 0.f)
                      + w1[mt] * fmaxf(acc[mt][nt][2], 0.f);
            p[nt][1] += w0[mt] * fmaxf(acc[mt][nt][1], 0.f)
                      + w1[mt] * fmaxf(acc[mt][nt][3], 0.f);
        }
    }
#pragma unroll
    for (int nt = 0; nt < 4; nt++) {
#pragma unroll
        for (int off = 4; off <= 16; off <<= 1) {
            p[nt][0] += __shfl_xor_sync(0xffffffffu, p[nt][0], off);
            p[nt][1] += __shfl_xor_sync(0xffffffffu, p[nt][1], off);
        }
    }

    if (lane < 4) {
        float* o = out + (size_t)(t0 + warp_m) * SQ + k0 + warp_n * 32;
#pragma unroll
        for (int nt = 0; nt < 4; nt++)
            *(float2*)(o + nt * 8 + lane * 2) = make_float2(p[nt][0], p[nt][1]);
    }
}

// ---------------------------------------------------------------------------
// launch
// ---------------------------------------------------------------------------
extern "C" void kernel_launch(void* const* d_in, const int* in_sizes, int n_in,
                              void* d_out, int out_size) {
    const float* x    = (const float*)d_in[0];   // [2048, 7168]
    const float* qr   = (const float*)d_in[1];   // [2048, 1536]
    const float* cosv = (const float*)d_in[2];   // [2048, 64]
    const float* sinv = (const float*)d_in[3];   // [2048, 64]
    const float* wqb  = (const float*)d_in[4];   // [1536, 8192]
    const float* wk   = (const float*)d_in[5];   // [7168, 128]
    const float* wpr  = (const float*)d_in[6];   // [7168, 64]
    const float* gam  = (const float*)d_in[7];   // [128]
    const float* bet  = (const float*)d_in[8];   // [128]
    float* out = (float*)d_out;

    float *kwp, *kwb;
    unsigned *q, *qrt, *xt, *wqt, *bkw, *ktf;
    cudaGetSymbolAddress((void**)&q,   g_q);
    cudaGetSymbolAddress((void**)&qrt, g_qrt);
    cudaGetSymbolAddress((void**)&xt,  g_xt);
    cudaGetSymbolAddress((void**)&wqt, g_wqt);
    cudaGetSymbolAddress((void**)&bkw, g_bkw);
    cudaGetSymbolAddress((void**)&kwp, g_kwp);
    cudaGetSymbolAddress((void**)&kwb, g_kw);
    cudaGetSymbolAddress((void**)&ktf, g_ktf);

    static bool attr_set = false;
    if (!attr_set) {
        cudaFuncSetAttribute(tc_gemm<true>,
                             cudaFuncAttributeMaxDynamicSharedMemorySize, SMEM_PIPE);
        cudaFuncSetAttribute(tc_gemm<false>,
                             cudaFuncAttributeMaxDynamicSharedMemorySize, SMEM_PIPE);
        cudaFuncSetAttribute(scores_tc,
                             cudaFuncAttributeMaxDynamicSharedMemorySize, SMEM_PIPE);
        attr_set = true;
    }

    // operand prep: tf32 + k-permute
    cvt_tf_perm<<<(TT * QL / 4) / 256, 256>>>(qr, qrt);
    cvt_tf_perm<<<(TT * DIM / 4) / 256, 256>>>(x, xt);
    transpose_tf<<<dim3(HHD / 32, QL / 32), dim3(32, 8)>>>(wqb, wqt);
    pack_kw<<<dim3(8, DIM / 32), dim3(32, 8)>>>(wk, wpr, bkw);

    // q = rope(qr @ Wq) -> tf32 bits, permuted (fused epilogue)
    tc_gemm<true><<<dim3(HHD / 128, TT / 128, 1), 256, SMEM_PIPE>>>(
        qrt, wqt, q, cosv, sinv, QL, HHD, QL / 32);
    // kp|w = x @ (Wk||Wproj): split-K=8 partials, then reduce
    tc_gemm<false><<<dim3(2, TT / 128, KSPL), 256, SMEM_PIPE>>>(
        xt, bkw, kwp, cosv, sinv, DIM, 256, DIM / 32 / KSPL);
    reduce_kw<<<(TT * 256 / 4) / 256, 256>>>(kwp, kwb);

    // layernorm + rope k -> tf32 bits, permuted
    ln_rope_k<<<TT, 128>>>(kwb, cosv, sinv, gam, bet, ktf);
    // scores
    scores_tc<<<dim3(SQ / 128, TT / 2), 256, SMEM_PIPE>>>(q, ktf, kwb, out);
}